// round 2
// baseline (speedup 1.0000x reference)
#include <cuda_runtime.h>
#include <cuda_bf16.h>

// Quadtree contraction:
//   out[b][i] = apply levels k=1..10 with choice c_k = bit_{k-1}(i):
//     c=0: g[r][c] = x[2r][2c] + x[2r][2c+1] + x[2r+1][2c]
//     c=1: g[r][c] = x[2r+1][2c+1]
// Stage 1: per (batch, 64x64 tile) block: levels 1..6 in shared memory,
//          producing 64 prefix scalars -> g_scratch[b][p][tr][tc] (16x16 grids).
// Stage 2: per (batch, prefix) block: levels 7..10 on the 16x16 grid,
//          writing out[b*1024 + (q<<6 | p)].

static __device__ float g_scratch[64 * 64 * 16 * 16]; // 4 MB: [b][p][tr][tc]

__global__ __launch_bounds__(256, 4) void cnndst_stage1(const float* __restrict__ M) {
    __shared__ float bufA[2048]; // level1 (2 grids of 32x32), then levels 3,5
    __shared__ float bufB[1024]; // level2 (4 grids of 16x16), then levels 4,6

    const int tile = blockIdx.x;       // 0..255
    const int b    = blockIdx.y;       // 0..63
    const int tr   = tile >> 4;
    const int tc   = tile & 15;
    const int tid  = threadIdx.x;

    const float* tbase = M + ((size_t)b << 20) + ((size_t)(tr << 6)) * 1024 + (size_t)(tc << 6);

    // Fused global load + level 0 -> 1.
    // 512 units: 32 coarse rows x 16 float4 col-chunks. Each unit: 2x float4
    // loads -> two 2x2 quads -> 2 S-values + 2 D-values into shared level-1.
    #pragma unroll
    for (int u = tid; u < 512; u += 256) {
        const int r  = u >> 4;     // coarse row 0..31
        const int c4 = u & 15;     // float4 chunk (fine cols 4*c4..4*c4+3)
        const float4 v0 = *(const float4*)(tbase + (size_t)(2 * r)     * 1024 + (c4 << 2));
        const float4 v1 = *(const float4*)(tbase + (size_t)(2 * r + 1) * 1024 + (c4 << 2));
        const float s0 = (v0.x + v0.y) + v1.x;   // quad at coarse col 2*c4
        const float s1 = (v0.z + v0.w) + v1.z;   // quad at coarse col 2*c4+1
        const int o = r * 32 + (c4 << 1);
        bufA[o]            = s0;
        bufA[o + 1]        = s1;
        bufA[1024 + o]     = v1.y;               // D children (prefix bit0 = 1)
        bufA[1024 + o + 1] = v1.w;
    }
    __syncthreads();

    // Levels j = 1..5: parent grid size g = 64>>j, P = 2^j parent grids.
    #pragma unroll
    for (int j = 1; j < 6; j++) {
        float* in = (j & 1) ? bufA : bufB;
        float* ob = (j & 1) ? bufB : bufA;
        const int g = 64 >> j;
        const int h = g >> 1;
        const int P = 1 << j;
        const int total = P * h * h;       // compile-time per unrolled iter
        for (int idx = tid; idx < total; idx += 256) {
            const int p   = idx / (h * h);
            const int rem = idx - p * (h * h);
            const int r   = rem / h;
            const int c   = rem - r * h;
            const float* q = in + p * g * g + (2 * r) * g + (2 * c);
            const float a  = q[0];
            const float bb = q[1];
            const float d0 = q[g];
            const float d1 = q[g + 1];
            ob[p * h * h + r * h + c]       = (a + bb) + d0;  // S: bit j of prefix = 0
            ob[(p + P) * h * h + r * h + c] = d1;             // D: bit j of prefix = 1
        }
        __syncthreads();
    }

    // Level 6 (64 scalars) lives in bufB (last loop iter j=5 wrote ob=bufB).
    if (tid < 64)
        g_scratch[((((b << 6) + tid) << 4) + tr) * 16 + tc] = bufB[tid];
}

__global__ __launch_bounds__(64, 16) void cnndst_stage2(float* __restrict__ out) {
    __shared__ float bufA[256]; // level6 grid (16x16), then levels 8, 10
    __shared__ float bufB[128]; // level7, then level 9

    const int bp  = blockIdx.x;   // b*64 + p
    const int tid = threadIdx.x;
    const float* src = g_scratch + ((size_t)bp << 8);

    #pragma unroll
    for (int k = tid; k < 256; k += 64) bufA[k] = src[k];
    __syncthreads();

    #pragma unroll
    for (int j = 0; j < 4; j++) {
        float* in = (j & 1) ? bufB : bufA;
        float* ob = (j & 1) ? bufA : bufB;
        const int g = 16 >> j;
        const int h = g >> 1;
        const int P = 1 << j;
        const int total = P * h * h;
        for (int idx = tid; idx < total; idx += 64) {
            const int p   = idx / (h * h);
            const int rem = idx - p * (h * h);
            const int r   = rem / h;
            const int c   = rem - r * h;
            const float* q = in + p * g * g + (2 * r) * g + (2 * c);
            ob[p * h * h + r * h + c]       = (q[0] + q[1]) + q[g];
            ob[(p + P) * h * h + r * h + c] = q[g + 1];
        }
        __syncthreads();
    }

    // Final 16 values in bufA (j=3 wrote ob=bufA). tid -> suffix q.
    const int b = bp >> 6;
    const int p = bp & 63;
    if (tid < 16)
        out[(b << 10) + (tid << 6) + p] = bufA[tid];
}

extern "C" void kernel_launch(void* const* d_in, const int* in_sizes, int n_in,
                              void* d_out, int out_size) {
    const float* M = (const float*)d_in[0];
    float* out = (float*)d_out;
    (void)in_sizes; (void)n_in; (void)out_size;

    cnndst_stage1<<<dim3(256, 64), 256>>>(M);
    cnndst_stage2<<<64 * 64, 64>>>(out);
}

// round 5
// speedup vs baseline: 1.1199x; 1.1199x over previous
#include <cuda_runtime.h>
#include <cuda_bf16.h>

// Quadtree contraction: out[b][i] applies, at level k=1..10 (finest first),
//   choice c_k = bit_{k-1}(i):  c=0 -> x[2r,2c]+x[2r,2c+1]+x[2r+1,2c]
//                               c=1 -> x[2r+1,2c+1]
// Stage 1: block = 4 tiles of 64x64. Levels 1..3 in registers (each thread
//          owns an 8x8 fine block -> 8 prefix scalars), levels 4..6 in shared.
//          Emits g_scratch[b][p6][tile] (16x16 grid per (b, 6-bit prefix)).
// Stage 2: one warp per (b,p6): 8 coalesced loads -> registers, levels 7..10
//          entirely via shfl_xor. Lane 0 writes 16 outputs.

static __device__ float g_scratch[64 * 64 * 256]; // 4 MB: [(b<<6|p6)<<8 | tile]

__global__ __launch_bounds__(256) void cnndst_stage1(const float* __restrict__ M) {
    __shared__ float bufA[2048]; // [q][p3(8)][t(64)] level3, later level5 out (q*128)
    __shared__ float bufB[1024]; // [q][p4(16)][cell(16)] level4 out

    const int tid = threadIdx.x;
    const int q   = tid >> 6;          // tile slot in block (0..3)
    const int t   = tid & 63;          // thread in tile -> (R8, C8)
    const int b   = blockIdx.y;
    const int tile = (blockIdx.x << 2) + q;   // 0..255
    const int tr  = tile >> 4;
    const int tc  = tile & 15;

    const float* src = M + ((size_t)b << 20)
                         + ((size_t)((tr << 6) + ((t >> 3) << 3))) * 1024
                         + (size_t)((tc << 6) + ((t & 7) << 3));

    // Levels 1..3 in registers over this thread's 8x8 fine block.
    // Input is read exactly once -> streaming loads (evict-first) so the
    // 256 MB stream doesn't evict g_scratch from L2 before stage 2.
    float s1[4][4], d1[4][4];
    #pragma unroll
    for (int rr = 0; rr < 4; rr++) {
        const float4 a0 = __ldcs((const float4*)(src + (size_t)(2 * rr) * 1024));
        const float4 a1 = __ldcs((const float4*)(src + (size_t)(2 * rr) * 1024 + 4));
        const float4 b0 = __ldcs((const float4*)(src + (size_t)(2 * rr + 1) * 1024));
        const float4 b1 = __ldcs((const float4*)(src + (size_t)(2 * rr + 1) * 1024 + 4));
        s1[rr][0] = (a0.x + a0.y) + b0.x;  d1[rr][0] = b0.y;
        s1[rr][1] = (a0.z + a0.w) + b0.z;  d1[rr][1] = b0.w;
        s1[rr][2] = (a1.x + a1.y) + b1.x;  d1[rr][2] = b1.y;
        s1[rr][3] = (a1.z + a1.w) + b1.z;  d1[rr][3] = b1.w;
    }
    // Level 2: grids p2 = 0:S(s1) 1:S(d1) 2:D(s1) 3:D(d1)
    float g2[4][2][2];
    #pragma unroll
    for (int r = 0; r < 2; r++)
        #pragma unroll
        for (int c = 0; c < 2; c++) {
            g2[0][r][c] = (s1[2*r][2*c] + s1[2*r][2*c+1]) + s1[2*r+1][2*c];
            g2[2][r][c] = s1[2*r+1][2*c+1];
            g2[1][r][c] = (d1[2*r][2*c] + d1[2*r][2*c+1]) + d1[2*r+1][2*c];
            g2[3][r][c] = d1[2*r+1][2*c+1];
        }
    // Level 3: v3[p2] = S child, v3[p2+4] = D child
    float v3[8];
    #pragma unroll
    for (int p = 0; p < 4; p++) {
        v3[p]     = (g2[p][0][0] + g2[p][0][1]) + g2[p][1][0];
        v3[p + 4] = g2[p][1][1];
    }
    #pragma unroll
    for (int p = 0; p < 8; p++)
        bufA[(q << 9) + (p << 6) + t] = v3[p];
    __syncthreads();

    // Level 4: 8 grids 8x8 -> 16 grids 4x4. 128 units/tile, 2 per thread.
    #pragma unroll
    for (int k = 0; k < 2; k++) {
        const int idx = tid + (k << 8);
        const int qq = idx >> 7, rem = idx & 127;
        const int p = rem >> 4, cell = rem & 15;
        const int r = cell >> 2, c = cell & 3;
        const float* in = bufA + (qq << 9) + (p << 6) + (r << 4) + (c << 1);
        float* ob = bufB + (qq << 8);
        ob[(p << 4) + cell]        = (in[0] + in[1]) + in[8];
        ob[((p + 8) << 4) + cell]  = in[9];
    }
    __syncthreads();

    // Level 5: 16 grids 4x4 -> 32 grids 2x2. 64 units/tile, 1 per thread.
    {
        const int qq = tid >> 6, rem = tid & 63;
        const int p = rem >> 2, cell = rem & 3;
        const int r = cell >> 1, c = cell & 1;
        const float* in = bufB + (qq << 8) + (p << 4) + (r << 3) + (c << 1);
        float* ob = bufA + (qq << 7);
        ob[(p << 2) + cell]        = (in[0] + in[1]) + in[4];
        ob[((p + 16) << 2) + cell] = in[5];
    }
    __syncthreads();

    // Level 6: 32 grids 2x2 -> 64 scalars. 32 units/tile -> 128 threads.
    if (tid < 128) {
        const int qq = tid >> 5, p = tid & 31;
        const int til = (blockIdx.x << 2) + qq;
        const float* in = bufA + (qq << 7) + (p << 2);
        const int base = (b << 6);
        g_scratch[((size_t)(base + p) << 8) + til]      = (in[0] + in[1]) + in[2];
        g_scratch[((size_t)(base + p + 32) << 8) + til] = in[3];
    }
}

// Stage 2: warp per (b,p6). 16x16 grid -> 4 levels via shuffles.
__global__ __launch_bounds__(256) void cnndst_stage2(float* __restrict__ out) {
    const int tid  = threadIdx.x;
    const int lane = tid & 31;
    const int bp   = (blockIdx.x << 3) + (tid >> 5);
    const float* src = g_scratch + ((size_t)bp << 8);

    // v[i] at lane l holds grid value k = i*32 + l; (r,c) = (k>>4, k&15).
    float v[8];
    #pragma unroll
    for (int i = 0; i < 8; i++) v[i] = src[(i << 5) + lane];

    const unsigned FULL = 0xffffffffu;

    // Level 7: 16x16 -> 2 grids 8x8. Valid at lanes {2C}; reg = row.
    float a1[2][8];
    #pragma unroll
    for (int R = 0; R < 8; R++) {
        const float x00 = v[R];
        const float x01 = __shfl_xor_sync(FULL, v[R], 1);
        const float x10 = __shfl_xor_sync(FULL, v[R], 16);
        const float x11 = __shfl_xor_sync(FULL, v[R], 17);
        a1[0][R] = (x00 + x01) + x10;   // S: prefix bit = 0
        a1[1][R] = x11;                 // D: prefix bit = 1
    }
    // Level 8: 2 grids 8x8 -> 4 grids 4x4. Valid lanes {4C}.
    float a2[4][4];
    #pragma unroll
    for (int p = 0; p < 2; p++)
        #pragma unroll
        for (int R = 0; R < 4; R++) {
            const float i0 = a1[p][2 * R];
            const float i1 = a1[p][2 * R + 1];
            a2[p][R]     = (i0 + __shfl_xor_sync(FULL, i0, 2)) + i1;
            a2[p + 2][R] = __shfl_xor_sync(FULL, i1, 2);
        }
    // Level 9: 4 grids 4x4 -> 8 grids 2x2. Valid lanes {0,8}.
    float a3[8][2];
    #pragma unroll
    for (int p = 0; p < 4; p++)
        #pragma unroll
        for (int R = 0; R < 2; R++) {
            const float i0 = a2[p][2 * R];
            const float i1 = a2[p][2 * R + 1];
            a3[p][R]     = (i0 + __shfl_xor_sync(FULL, i0, 4)) + i1;
            a3[p + 4][R] = __shfl_xor_sync(FULL, i1, 4);
        }
    // Level 10: 8 grids 2x2 -> 16 scalars. Valid lane 0.
    float a4[16];
    #pragma unroll
    for (int p = 0; p < 8; p++) {
        const float i0 = a3[p][0];
        const float i1 = a3[p][1];
        a4[p]     = (i0 + __shfl_xor_sync(FULL, i0, 8)) + i1;
        a4[p + 8] = __shfl_xor_sync(FULL, i1, 8);
    }

    if (lane == 0) {
        const int b = bp >> 6;
        const int p = bp & 63;
        float* o = out + (b << 10) + p;
        #pragma unroll
        for (int s = 0; s < 16; s++) o[s << 6] = a4[s];
    }
}

extern "C" void kernel_launch(void* const* d_in, const int* in_sizes, int n_in,
                              void* d_out, int out_size) {
    const float* M = (const float*)d_in[0];
    float* out = (float*)d_out;
    (void)in_sizes; (void)n_in; (void)out_size;

    cnndst_stage1<<<dim3(64, 64), 256>>>(M);
    cnndst_stage2<<<512, 256>>>(out);
}

// round 7
// speedup vs baseline: 1.1673x; 1.0423x over previous
#include <cuda_runtime.h>
#include <cuda_bf16.h>

// Quadtree contraction: out[b][i] applies, at level k=1..10 (finest first),
//   choice c_k = bit_{k-1}(i):  c=0 -> x[2r,2c]+x[2r,2c+1]+x[2r+1,2c]
//                               c=1 -> x[2r+1,2c+1]
// Stage 1: block = one 128x128 tile. Levels 1..3 in registers (thread owns an
//          8x8 fine block), levels 4..7 in shared. Emits g_scratch[b][p7][tile]
//          (8x8 grid per (b, 7-bit prefix)). 2 MB scratch.
// Stage 2: one warp per (b,p7): 2 coalesced loads, levels 8..10 via shfl_xor.

static __device__ float g_scratch[64 * 128 * 64]; // 2 MB: [((b<<7)|p7)<<6 | tile]

__global__ __launch_bounds__(256) void cnndst_stage1(const float* __restrict__ M) {
    __shared__ float bufA[2048]; // level3 [p3(8)][t(256)], later level5 (512)
    __shared__ float bufB[1024]; // level4 [p4(16)][cell(64)], later level6 (256)

    const int tid  = threadIdx.x;
    const int b    = blockIdx.y;
    const int tile = blockIdx.x;       // 0..63
    const int tr   = tile >> 3;
    const int tc   = tile & 7;

    // Thread's 8x8 fine block at rows (tid>>4)*8, cols (tid&15)*8 of the tile.
    const float* src = M + ((size_t)b << 20)
                         + ((size_t)((tr << 7) + ((tid >> 4) << 3))) * 1024
                         + (size_t)((tc << 7) + ((tid & 15) << 3));

    // Front-batched streaming loads (read-once input; evict-first).
    float4 L[16];
    #pragma unroll
    for (int rr = 0; rr < 8; rr++) {
        L[2 * rr]     = __ldcs((const float4*)(src + (size_t)rr * 1024));
        L[2 * rr + 1] = __ldcs((const float4*)(src + (size_t)rr * 1024 + 4));
    }

    // Level 1 in registers: 4x4 S grid + 4x4 D grid.
    float s1[4][4], d1[4][4];
    #pragma unroll
    for (int rr = 0; rr < 4; rr++) {
        const float4 a0 = L[4 * rr],     a1 = L[4 * rr + 1];
        const float4 b0 = L[4 * rr + 2], b1 = L[4 * rr + 3];
        s1[rr][0] = (a0.x + a0.y) + b0.x;  d1[rr][0] = b0.y;
        s1[rr][1] = (a0.z + a0.w) + b0.z;  d1[rr][1] = b0.w;
        s1[rr][2] = (a1.x + a1.y) + b1.x;  d1[rr][2] = b1.y;
        s1[rr][3] = (a1.z + a1.w) + b1.z;  d1[rr][3] = b1.w;
    }
    // Level 2: p2 = c1 + 2*c2 -> grids 0:S(s1) 1:S(d1) 2:D(s1) 3:D(d1).
    float g2[4][2][2];
    #pragma unroll
    for (int r = 0; r < 2; r++)
        #pragma unroll
        for (int c = 0; c < 2; c++) {
            g2[0][r][c] = (s1[2*r][2*c] + s1[2*r][2*c+1]) + s1[2*r+1][2*c];
            g2[2][r][c] = s1[2*r+1][2*c+1];
            g2[1][r][c] = (d1[2*r][2*c] + d1[2*r][2*c+1]) + d1[2*r+1][2*c];
            g2[3][r][c] = d1[2*r+1][2*c+1];
        }
    // Level 3: v3[p2] = S, v3[p2+4] = D. Thread sits at (tid>>4, tid&15) of 16x16.
    #pragma unroll
    for (int p = 0; p < 4; p++) {
        bufA[(p << 8) + tid]       = (g2[p][0][0] + g2[p][0][1]) + g2[p][1][0];
        bufA[((p + 4) << 8) + tid] = g2[p][1][1];
    }
    __syncthreads();

    // Level 4: 8 grids 16x16 -> 16 grids 8x8. 512 units, 2/thread.
    #pragma unroll
    for (int k = 0; k < 2; k++) {
        const int idx  = tid + (k << 8);
        const int p    = idx >> 6, cell = idx & 63;
        const int r    = cell >> 3, c = cell & 7;
        const float* in = bufA + (p << 8) + (r << 5) + (c << 1);
        bufB[(p << 6) + cell]       = (in[0] + in[1]) + in[16];
        bufB[((p + 8) << 6) + cell] = in[17];
    }
    __syncthreads();

    // Level 5: 16 grids 8x8 -> 32 grids 4x4. 256 units, 1/thread.
    {
        const int p = tid >> 4, cell = tid & 15;
        const int r = cell >> 2, c = cell & 3;
        const float* in = bufB + (p << 6) + (r << 4) + (c << 1);
        bufA[(p << 4) + cell]        = (in[0] + in[1]) + in[8];
        bufA[((p + 16) << 4) + cell] = in[9];
    }
    __syncthreads();

    // Level 6: 32 grids 4x4 -> 64 grids 2x2. 128 units.
    if (tid < 128) {
        const int p = tid >> 2, cell = tid & 3;
        const int r = cell >> 1, c = cell & 1;
        const float* in = bufA + (p << 4) + (r << 3) + (c << 1);
        bufB[(p << 2) + cell]        = (in[0] + in[1]) + in[4];
        bufB[((p + 32) << 2) + cell] = in[5];
    }
    __syncthreads();

    // Level 7: 64 grids 2x2 -> 128 scalars -> g_scratch.
    if (tid < 64) {
        const float* in = bufB + (tid << 2);
        const int base = (b << 7);
        g_scratch[((size_t)(base + tid) << 6) + tile]      = (in[0] + in[1]) + in[2];
        g_scratch[((size_t)(base + tid + 64) << 6) + tile] = in[3];
    }
}

// Stage 2: warp per (b,p7). 8x8 grid -> levels 8..10 via shuffles.
// Lane layout: k = reg*32 + lane, (r,c) = (k>>3, k&7).
__global__ __launch_bounds__(256) void cnndst_stage2(float* __restrict__ out) {
    const int tid  = threadIdx.x;
    const int lane = tid & 31;
    const int bp   = (blockIdx.x << 3) + (tid >> 5);   // b*128 + p7
    const float* src = g_scratch + ((size_t)bp << 6);

    float v[2];
    v[0] = src[lane];
    v[1] = src[32 + lane];

    const unsigned FULL = 0xffffffffu;

    // Level 8: 8x8 -> 2 grids 4x4 (results valid at even r, even c lanes).
    float a1[2][2];
    #pragma unroll
    for (int i = 0; i < 2; i++) {
        const float x00 = v[i];
        const float x01 = __shfl_xor_sync(FULL, v[i], 1);
        const float x10 = __shfl_xor_sync(FULL, v[i], 8);
        const float x11 = __shfl_xor_sync(FULL, v[i], 9);
        a1[0][i] = (x00 + x01) + x10;   // c8 = 0
        a1[1][i] = x11;                 // c8 = 1
    }
    // Level 9: 4x4 -> 2x2 per grid (sparse spacing 2: xor 2 horiz, 16 vert).
    float a2[4][2];
    #pragma unroll
    for (int p = 0; p < 2; p++)
        #pragma unroll
        for (int i = 0; i < 2; i++) {
            const float x00 = a1[p][i];
            const float x01 = __shfl_xor_sync(FULL, x00, 2);
            const float x10 = __shfl_xor_sync(FULL, x00, 16);
            const float x11 = __shfl_xor_sync(FULL, x00, 18);
            a2[p][i]     = (x00 + x01) + x10;   // c9 = 0
            a2[p + 2][i] = x11;                 // c9 = 1
        }
    // Level 10: 2x2 -> scalar (sparse spacing 4: xor 4 horiz; vert = cross-reg).
    float a4[8];
    #pragma unroll
    for (int p = 0; p < 4; p++) {
        const float i0 = a2[p][0];   // r'' = 0 row
        const float i1 = a2[p][1];   // r'' = 1 row
        a4[p]     = (i0 + __shfl_xor_sync(FULL, i0, 4)) + i1;   // c10 = 0
        a4[p + 4] = __shfl_xor_sync(FULL, i1, 4);               // c10 = 1
    }

    if (lane == 0) {
        const int b  = bp >> 7;
        const int p7 = bp & 127;
        float* o = out + (b << 10) + p7;
        #pragma unroll
        for (int q = 0; q < 8; q++) o[q << 7] = a4[q];
    }
}

extern "C" void kernel_launch(void* const* d_in, const int* in_sizes, int n_in,
                              void* d_out, int out_size) {
    const float* M = (const float*)d_in[0];
    float* out = (float*)d_out;
    (void)in_sizes; (void)n_in; (void)out_size;

    cnndst_stage1<<<dim3(64, 64), 256>>>(M);
    cnndst_stage2<<<1024, 256>>>(out);
}